// round 3
// baseline (speedup 1.0000x reference)
#include <cuda_runtime.h>

#define NSTEP 255

__device__ float g_wz[8 * 128 * 128];
__device__ float g_ring[2 * 255 * 64];
__device__ float g_cond[255 * 2 * 1024];
__device__ float g_ds1[2 * 64 * 512];
__device__ float g_ds2[2 * 64 * 256];
__device__ float g_outpre[2 * 64 * 256];
__device__ float g_up1[2 * 64 * 512];
__device__ float g_up2[2 * 64 * 1024];

// ---- transpose w_dil (8,128,64,2) -> g_wz[l][o][t*64+r] -------------------
__global__ void k_wprep(const float* __restrict__ wdil) {
    int idx = blockIdx.x * blockDim.x + threadIdx.x;
    if (idx < 8 * 128 * 128) {
        int r = idx & 63, t = (idx >> 6) & 1, o = (idx >> 7) & 127, l = idx >> 14;
        g_wz[idx] = wdil[((l * 128 + o) * 64 + r) * 2 + t];
    }
}

// ---- down conv: out[b][o][l] = sum_{c,k} w[o][c][k] in[b][c][2l+k] --------
__global__ void k_down(int sel, const float* __restrict__ w,
                       const float* __restrict__ song) {
    int o = blockIdx.x, b = blockIdx.y;
    int Lout = sel ? 256 : 512;
    const float* in = sel ? g_ds1 : song;
    float* out = sel ? g_ds2 : g_ds1;
    __shared__ float wr[128];
    if (threadIdx.x < 128) wr[threadIdx.x] = w[o * 128 + threadIdx.x];
    __syncthreads();
    const float* xin = in + b * 64 * (2 * Lout);
    for (int l = threadIdx.x; l < Lout; l += blockDim.x) {
        float acc = 0.f;
#pragma unroll
        for (int c = 0; c < 64; c++)
            acc += wr[2 * c] * xin[c * 2 * Lout + 2 * l]
                 + wr[2 * c + 1] * xin[c * 2 * Lout + 2 * l + 1];
        out[(b * 64 + o) * Lout + l] = acc;
    }
}

// ---- up conv: out[b][o][2l+k] = sum_i w[i][o][k] in[b][i][l] --------------
__global__ void k_up(int sel, const float* __restrict__ w) {
    int o = blockIdx.x, b = blockIdx.y;
    int Lin = sel ? 512 : 256;
    const float* in = sel ? g_up1 : g_outpre;
    float* out = sel ? g_up2 : g_up1;
    __shared__ float wr[128];
    if (threadIdx.x < 128) {
        int i = threadIdx.x >> 1, k = threadIdx.x & 1;
        wr[threadIdx.x] = w[(i * 64 + o) * 2 + k];
    }
    __syncthreads();
    for (int l = threadIdx.x; l < Lin; l += blockDim.x) {
        float a0 = 0.f, a1 = 0.f;
#pragma unroll
        for (int i = 0; i < 64; i++) {
            float x = in[(b * 64 + i) * Lin + l];
            a0 += wr[2 * i] * x; a1 += wr[2 * i + 1] * x;
        }
        out[(b * 64 + o) * 2 * Lin + 2 * l] = a0;
        out[(b * 64 + o) * 2 * Lin + 2 * l + 1] = a1;
    }
}

// ---- batchnorm over (batch,length) per channel, + relu --------------------
__global__ void k_bnrelu(int sel, const float* __restrict__ gamma,
                         const float* __restrict__ beta, float* __restrict__ hout) {
    int L = (sel == 1) ? 256 : (sel == 3 ? 1024 : 512);
    const float* in = (sel == 0) ? g_ds1 : (sel == 1) ? g_ds2
                    : (sel == 2) ? g_up1 : g_up2;
    float* out = (sel == 0) ? g_ds1 : (sel == 1) ? g_ds2
               : (sel == 2) ? g_up1 : hout;
    int ch = blockIdx.x, tid = threadIdx.x;
    float s = 0.f, q = 0.f;
    for (int i = tid; i < 2 * L; i += 256) {
        int b = i >= L, l = i - b * L;
        float x = in[(b * 64 + ch) * L + l];
        s += x; q += x * x;
    }
    __shared__ float rs[256], rq[256];
    rs[tid] = s; rq[tid] = q; __syncthreads();
    for (int st = 128; st > 0; st >>= 1) {
        if (tid < st) { rs[tid] += rs[tid + st]; rq[tid] += rq[tid + st]; }
        __syncthreads();
    }
    __shared__ float mm, iv;
    if (tid == 0) {
        float m = rs[0] / (2.f * L);
        mm = m; iv = rsqrtf(rq[0] / (2.f * L) - m * m + 1e-5f);
    }
    __syncthreads();
    float m = mm, inv = iv, ga = gamma[ch], be = beta[ch];
    for (int i = tid; i < 2 * L; i += 256) {
        int b = i >= L, l = i - b * L;
        float x = in[(b * 64 + ch) * L + l];
        out[(b * 64 + ch) * L + l] = fmaxf(ga * (x - m) * inv + be, 0.f);
    }
}

// ---- cond GEMM: g_cond[n][b][o] = w_cond[o] . ds2[b][:][n] ---------------
__global__ void k_cond(const float* __restrict__ wcond) {
    __shared__ __align__(16) float wt[128 * 64];
    __shared__ __align__(16) float col[128];
    int ob = blockIdx.x * 128, tid = threadIdx.x;
    for (int i = tid; i < 128 * 64; i += 256) wt[i] = wcond[ob * 64 + i];
    for (int nn = 0; nn < 16; nn++) {
        int n = blockIdx.y * 16 + nn;
        if (n >= NSTEP) break;
        __syncthreads();
        if (tid < 128) {
            int b = tid >> 6, c = tid & 63;
            col[tid] = g_ds2[(b * 64 + c) * 256 + n];
        }
        __syncthreads();
        int oo = tid >> 1, b = tid & 1;
        const float4* w4 = (const float4*)(wt + oo * 64);
        const float4* c4 = (const float4*)(col + b * 64);
        float acc = 0.f;
#pragma unroll
        for (int j = 0; j < 16; j++) {
            float4 a = w4[j], x = c4[j];
            acc += a.x * x.x + a.y * x.y + a.z * x.z + a.w * x.w;
        }
        g_cond[(n * 2 + b) * 1024 + ob + oo] = acc;
    }
}

// ---- autoregressive loop: one CTA per batch -------------------------------
__global__ void __launch_bounds__(1024, 1)
k_loop(const float* __restrict__ wembed, const float* __restrict__ wres,
       const float* __restrict__ wskip, const float* __restrict__ wout,
       const float* __restrict__ wend) {
    const int b = blockIdx.x, tid = threadIdx.x;
    __shared__ __align__(16) float sc[1024], oldv[512], z[128], gv[64];
    __shared__ __align__(16) float skipv[256], hb[256], h2[256];
    __shared__ __align__(16) float tb[2][64], yv[64];

    float* ring = g_ring + b * 255 * 64;
    float* outp = g_outpre + b * 64 * 256;
    for (int i = tid; i < 255 * 64; i += 1024) ring[i] = 0.f;
    if (tid < 64) { yv[tid] = 0.f; outp[tid * 256] = 0.f; }
    if (tid < 256) skipv[tid] = 0.f;
    __syncthreads();

    const int DILa[8] = {1, 2, 4, 8, 16, 32, 64, 128};
    const int Roff[8] = {0, 1, 3, 7, 15, 31, 63, 127};

    for (int n = 0; n < NSTEP; n++) {
        sc[tid] = g_cond[(n * 2 + b) * 1024 + tid];
        if (tid < 512) {
            int l = tid >> 6, r = tid & 63;
            oldv[tid] = ring[(Roff[l] + (n & (DILa[l] - 1))) * 64 + r];
        } else {
            int t2 = tid - 512, o = t2 >> 3, p = t2 & 7;
            const float4* w4 = (const float4*)(wembed + o * 64 + p * 8);
            const float4* v4 = (const float4*)(yv + p * 8);
            float4 a0 = w4[0], x0 = v4[0], a1 = w4[1], x1 = v4[1];
            float acc = a0.x * x0.x + a0.y * x0.y + a0.z * x0.z + a0.w * x0.w
                      + a1.x * x1.x + a1.y * x1.y + a1.z * x1.z + a1.w * x1.w;
            acc += __shfl_xor_sync(~0u, acc, 1);
            acc += __shfl_xor_sync(~0u, acc, 2);
            acc += __shfl_xor_sync(~0u, acc, 4);
            if (p == 0) tb[0][o] = acc;
        }
        __syncthreads();

        int cb = 0;
#pragma unroll
        for (int l = 0; l < 8; l++) {
            const int d = DILa[l];
            float* tc = tb[cb];
            if (tid < 64) ring[(Roff[l] + (n & (d - 1))) * 64 + tid] = tc[tid];
            {   // z = Wz @ [t_old ; t_cur] + cond
                int o = tid >> 3, p = tid & 7;
                const float* vs = (p < 4) ? (oldv + l * 64 + p * 16)
                                          : ((const float*)tc + (p - 4) * 16);
                const float4* w4 = (const float4*)(g_wz + (l * 128 + o) * 128 + p * 16);
                const float4* v4 = (const float4*)vs;
                float acc = 0.f;
#pragma unroll
                for (int j = 0; j < 4; j++) {
                    float4 a = w4[j], x = v4[j];
                    acc += a.x * x.x + a.y * x.y + a.z * x.z + a.w * x.w;
                }
                acc += __shfl_xor_sync(~0u, acc, 1);
                acc += __shfl_xor_sync(~0u, acc, 2);
                acc += __shfl_xor_sync(~0u, acc, 4);
                if (p == 0) z[o] = acc + sc[l * 128 + o];
            }
            __syncthreads();
            if (tid < 64) {
                float a = z[tid], c = z[64 + tid];
                gv[tid] = tanhf(a) * (1.f / (1.f + expf(-c)));
            }
            __syncthreads();
            if (l < 7 && tid < 256) {   // residual
                int o = tid >> 2, p = tid & 3;
                const float4* w4 = (const float4*)(wres + (l * 64 + o) * 64 + p * 16);
                const float4* v4 = (const float4*)(gv + p * 16);
                float acc = 0.f;
#pragma unroll
                for (int j = 0; j < 4; j++) {
                    float4 a = w4[j], x = v4[j];
                    acc += a.x * x.x + a.y * x.y + a.z * x.z + a.w * x.w;
                }
                acc += __shfl_xor_sync(~0u, acc, 1);
                acc += __shfl_xor_sync(~0u, acc, 2);
                if (p == 0) tb[cb ^ 1][o] = tc[o] + acc;
            }
            if (tid >= 256 && tid < 768) {   // skip accumulation
                int t2 = tid - 256, s = t2 >> 1, p = t2 & 1;
                const float4* w4 = (const float4*)(wskip + (l * 256 + s) * 64 + p * 32);
                const float4* v4 = (const float4*)(gv + p * 32);
                float acc = 0.f;
#pragma unroll
                for (int j = 0; j < 8; j++) {
                    float4 a = w4[j], x = v4[j];
                    acc += a.x * x.x + a.y * x.y + a.z * x.z + a.w * x.w;
                }
                acc += __shfl_xor_sync(~0u, acc, 1);
                if (p == 0) skipv[s] += acc;
            }
            __syncthreads();
            if (l < 7) cb ^= 1;
        }

        if (tid < 256) { hb[tid] = fmaxf(skipv[tid], 0.f); skipv[tid] = 0.f; }
        __syncthreads();
        {   // h2 = relu(w_out @ relu(skip))
            int o = tid >> 2, p = tid & 3;
            const float4* w4 = (const float4*)(wout + o * 256 + p * 64);
            const float4* v4 = (const float4*)(hb + p * 64);
            float acc = 0.f;
#pragma unroll
            for (int j = 0; j < 16; j++) {
                float4 a = w4[j], x = v4[j];
                acc += a.x * x.x + a.y * x.y + a.z * x.z + a.w * x.w;
            }
            acc += __shfl_xor_sync(~0u, acc, 1);
            acc += __shfl_xor_sync(~0u, acc, 2);
            if (p == 0) h2[o] = fmaxf(acc, 0.f);
        }
        __syncthreads();
        {   // y = w_end @ h2
            int o = tid >> 4, p = tid & 15;
            const float4* w4 = (const float4*)(wend + o * 256 + p * 16);
            const float4* v4 = (const float4*)(h2 + p * 16);
            float acc = 0.f;
#pragma unroll
            for (int j = 0; j < 4; j++) {
                float4 a = w4[j], x = v4[j];
                acc += a.x * x.x + a.y * x.y + a.z * x.z + a.w * x.w;
            }
            acc += __shfl_xor_sync(~0u, acc, 1);
            acc += __shfl_xor_sync(~0u, acc, 2);
            acc += __shfl_xor_sync(~0u, acc, 4);
            acc += __shfl_xor_sync(~0u, acc, 8);
            if (p == 0) { yv[o] = acc; outp[o * 256 + n + 1] = acc; }
        }
        __syncthreads();
    }
}

extern "C" void kernel_launch(void* const* d_in, const int* in_sizes, int n_in,
                              void* d_out, int out_size) {
    const float* song   = (const float*)d_in[0];
    const float* ds_w   = (const float*)d_in[1];
    const float* ds_g   = (const float*)d_in[2];
    const float* ds_b   = (const float*)d_in[3];
    const float* us_w   = (const float*)d_in[4];
    const float* us_g   = (const float*)d_in[5];
    const float* us_b   = (const float*)d_in[6];
    const float* wembed = (const float*)d_in[7];
    const float* wcond  = (const float*)d_in[8];
    const float* wdil   = (const float*)d_in[9];
    const float* wres   = (const float*)d_in[10];
    const float* wskip  = (const float*)d_in[11];
    const float* wout   = (const float*)d_in[12];
    const float* wend   = (const float*)d_in[13];
    float* out = (float*)d_out;

    k_wprep<<<512, 256>>>(wdil);
    k_down<<<dim3(64, 2), 256>>>(0, ds_w, song);
    k_bnrelu<<<64, 256>>>(0, ds_g, ds_b, nullptr);
    k_down<<<dim3(64, 2), 256>>>(1, ds_w + 8192, song);
    k_bnrelu<<<64, 256>>>(1, ds_g + 64, ds_b + 64, nullptr);
    k_cond<<<dim3(8, 16), 256>>>(wcond);
    k_loop<<<2, 1024>>>(wembed, wres, wskip, wout, wend);
    k_up<<<dim3(64, 2), 256>>>(0, us_w);
    k_bnrelu<<<64, 256>>>(2, us_g, us_b, nullptr);
    k_up<<<dim3(64, 2), 256>>>(1, us_w + 8192);
    k_bnrelu<<<64, 256>>>(3, us_g + 64, us_b + 64, out);
}

// round 6
// speedup vs baseline: 1.1726x; 1.1726x over previous
#include <cuda_runtime.h>

#define NSTEP 255

__device__ float g_wz[8 * 128 * 128];
__device__ float g_cond[NSTEP * 2 * 1024];
__device__ float g_ds1[2 * 64 * 512];
__device__ float g_ds2[2 * 64 * 256];
__device__ float g_outpre[2 * 64 * 256];
__device__ float g_up1[2 * 64 * 512];

__device__ __forceinline__ float dot4(float4 a, float4 x) {
    return a.x * x.x + a.y * x.y + a.z * x.z + a.w * x.w;
}
#define BARS(id, n) asm volatile("bar.sync %0,%1;" ::"r"(id), "r"(n) : "memory")
#define BARA(id, n) asm volatile("bar.arrive %0,%1;" ::"r"(id), "r"(n) : "memory")

// ---- fused down-conv + batchnorm + relu (block = one output channel) ------
__global__ void k_downbn(int sel, const float* __restrict__ w,
                         const float* __restrict__ song,
                         const float* __restrict__ gamma,
                         const float* __restrict__ beta) {
    int o = blockIdx.x, tid = threadIdx.x;
    int Lout = sel ? 256 : 512;
    const float* in = sel ? g_ds1 : song;
    float* out = sel ? g_ds2 : g_ds1;
    __shared__ float wr[128], rs[256], rq[256];
    if (tid < 128) wr[tid] = w[o * 128 + tid];
    __syncthreads();
    float vals[4];
    int cnt = 2 * Lout / 256;
    float s = 0.f, q = 0.f;
    for (int j = 0; j < cnt; j++) {
        int i = tid + j * 256, bb = i >= Lout, l = i - bb * Lout;
        const float* xin = in + bb * 64 * 2 * Lout;
        float acc = 0.f;
#pragma unroll
        for (int c = 0; c < 64; c++)
            acc += wr[2 * c] * xin[c * 2 * Lout + 2 * l]
                 + wr[2 * c + 1] * xin[c * 2 * Lout + 2 * l + 1];
        vals[j] = acc; s += acc; q += acc * acc;
    }
    rs[tid] = s; rq[tid] = q; __syncthreads();
    for (int st = 128; st; st >>= 1) {
        if (tid < st) { rs[tid] += rs[tid + st]; rq[tid] += rq[tid + st]; }
        __syncthreads();
    }
    float m = rs[0] / (2.f * Lout);
    float inv = rsqrtf(rq[0] / (2.f * Lout) - m * m + 1e-5f);
    float ga = gamma[o], be = beta[o];
    for (int j = 0; j < cnt; j++) {
        int i = tid + j * 256, bb = i >= Lout, l = i - bb * Lout;
        out[(bb * 64 + o) * Lout + l] = fmaxf(ga * (vals[j] - m) * inv + be, 0.f);
    }
}

// ---- fused up-conv + batchnorm + relu -------------------------------------
__global__ void k_upbn(int sel, const float* __restrict__ w,
                       const float* __restrict__ gamma,
                       const float* __restrict__ beta, float* __restrict__ hout) {
    int o = blockIdx.x, tid = threadIdx.x;
    int Lin = sel ? 512 : 256;
    const float* in = sel ? g_up1 : g_outpre;
    float* out = sel ? hout : g_up1;
    __shared__ float wr[128], rs[256], rq[256];
    if (tid < 128) { int i = tid >> 1, k = tid & 1; wr[tid] = w[(i * 64 + o) * 2 + k]; }
    __syncthreads();
    int cnt = 2 * Lin / 256;
    float v0[4], v1[4];
    float s = 0.f, q = 0.f;
    for (int j = 0; j < cnt; j++) {
        int i = tid + j * 256, bb = i >= Lin, l = i - bb * Lin;
        float a0 = 0.f, a1 = 0.f;
#pragma unroll
        for (int c = 0; c < 64; c++) {
            float x = in[(bb * 64 + c) * Lin + l];
            a0 += wr[2 * c] * x; a1 += wr[2 * c + 1] * x;
        }
        v0[j] = a0; v1[j] = a1;
        s += a0 + a1; q += a0 * a0 + a1 * a1;
    }
    rs[tid] = s; rq[tid] = q; __syncthreads();
    for (int st = 128; st; st >>= 1) {
        if (tid < st) { rs[tid] += rs[tid + st]; rq[tid] += rq[tid + st]; }
        __syncthreads();
    }
    float m = rs[0] / (4.f * Lin);
    float inv = rsqrtf(rq[0] / (4.f * Lin) - m * m + 1e-5f);
    float ga = gamma[o], be = beta[o];
    for (int j = 0; j < cnt; j++) {
        int i = tid + j * 256, bb = i >= Lin, l = i - bb * Lin;
        float* op = out + (bb * 64 + o) * 2 * Lin + 2 * l;
        op[0] = fmaxf(ga * (v0[j] - m) * inv + be, 0.f);
        op[1] = fmaxf(ga * (v1[j] - m) * inv + be, 0.f);
    }
}

// ---- transpose w_dil (8,128,64,2) -> g_wz[l][o][t*64+r] -------------------
__global__ void k_wprep(const float* __restrict__ wdil) {
    int idx = blockIdx.x * blockDim.x + threadIdx.x;
    if (idx < 8 * 128 * 128) {
        int r = idx & 63, t = (idx >> 6) & 1, o = (idx >> 7) & 127, l = idx >> 14;
        g_wz[idx] = wdil[((l * 128 + o) * 64 + r) * 2 + t];
    }
}

// ---- cond GEMM: g_cond[n][b][o] = w_cond[o] . ds2[b][:][n] ----------------
__global__ void k_cond(const float* __restrict__ wcond) {
    __shared__ __align__(16) float wt[128 * 64];
    __shared__ __align__(16) float col[128];
    int ob = blockIdx.x * 128, tid = threadIdx.x;
    for (int i = tid; i < 128 * 64; i += 256) wt[i] = wcond[ob * 64 + i];
    for (int nn = 0; nn < 16; nn++) {
        int n = blockIdx.y * 16 + nn;
        if (n >= NSTEP) break;
        __syncthreads();
        if (tid < 128) {
            int b = tid >> 6, c = tid & 63;
            col[tid] = g_ds2[(b * 64 + c) * 256 + n];
        }
        __syncthreads();
        int oo = tid >> 1, b = tid & 1;
        const float4* w4 = (const float4*)(wt + oo * 64);
        const float4* c4 = (const float4*)(col + b * 64);
        float acc = 0.f;
#pragma unroll
        for (int j = 0; j < 16; j++) acc += dot4(w4[j], c4[j]);
        g_cond[(n * 2 + b) * 1024 + ob + oo] = acc;
    }
}

__global__ void k_zero() {
    if (threadIdx.x < 128) g_outpre[threadIdx.x * 256] = 0.f;
}

// ---- autoregressive loop: one CTA per batch, warp-specialized -------------
#define S_RING 0
#define S_SC   16320
#define S_GVB  18368
#define S_TCB  18880
#define S_SKIP 19456
#define S_HB   19712
#define S_H2   19968
#define S_YV   20224
#define S_TOT  20288

__constant__ int c_dil[8]  = {1, 2, 4, 8, 16, 32, 64, 128};
__constant__ int c_roff[8] = {0, 1, 3, 7, 15, 31, 63, 127};

__global__ void __launch_bounds__(1024, 1)
k_loop(const float* __restrict__ wembed, const float* __restrict__ wres,
       const float* __restrict__ wskip, const float* __restrict__ wout,
       const float* __restrict__ wend) {
    extern __shared__ float sm[];
    float* ring  = sm + S_RING;
    float* sc    = sm + S_SC;
    float* gvb   = sm + S_GVB;
    float* tcb   = sm + S_TCB;
    float* skipv = sm + S_SKIP;
    float* hb    = sm + S_HB;
    float* h2    = sm + S_H2;
    float* yv    = sm + S_YV;
    const int b = blockIdx.x, tid = threadIdx.x;

    for (int i = tid; i < 16320; i += 1024) ring[i] = 0.f;
    sc[tid] = g_cond[b * 1024 + tid];            // cond for step 0
    if (tid < 64) yv[tid] = 0.f;
    if (tid < 256) skipv[tid] = 0.f;
    __syncthreads();

    if (tid < 512) {
        // ------------- group A: critical path --------------------------
        const int o = tid >> 3, p = tid & 7;
        for (int n = 0; n < NSTEP; n++) {
            const float* scur = sc + (n & 1) * 1024;
            {   // embed: tc0 = wembed @ y_{n-1}
                const float4* w4 = (const float4*)(wembed + o * 64 + p * 8);
                const float4* v4 = (const float4*)(yv + p * 8);
                float acc = dot4(w4[0], v4[0]) + dot4(w4[1], v4[1]);
                acc += __shfl_xor_sync(~0u, acc, 1);
                acc += __shfl_xor_sync(~0u, acc, 2);
                acc += __shfl_xor_sync(~0u, acc, 4);
                if (p == 0) tcb[o] = acc;
            }
            BARS(11, 512);
#pragma unroll
            for (int l = 0; l < 8; l++) {
                const int slot = c_roff[l] + (n & (c_dil[l] - 1));
                float a0 = 0.f, a1 = 0.f;
                const float4* wa = (const float4*)(g_wz + (l * 128 + o) * 128 + p * 16);
                const float4* wb = (const float4*)(g_wz + (l * 128 + 64 + o) * 128 + p * 16);
                const float4* v4 = (p < 4)
                    ? (const float4*)(ring + slot * 64 + p * 16)
                    : (const float4*)(tcb + l * 64 + (p - 4) * 16);
#pragma unroll
                for (int j = 0; j < 4; j++) {
                    float4 x = v4[j];
                    a0 += dot4(wa[j], x); a1 += dot4(wb[j], x);
                }
                a0 += __shfl_xor_sync(~0u, a0, 1); a1 += __shfl_xor_sync(~0u, a1, 1);
                a0 += __shfl_xor_sync(~0u, a0, 2); a1 += __shfl_xor_sync(~0u, a1, 2);
                a0 += __shfl_xor_sync(~0u, a0, 4); a1 += __shfl_xor_sync(~0u, a1, 4);
                if (p == 0) {
                    float z0 = a0 + scur[l * 128 + o];
                    float z1 = a1 + scur[l * 128 + 64 + o];
                    float e0 = __expf(2.f * z0), e1 = __expf(-z1);
                    gvb[l * 64 + o] = (1.f - __fdividef(2.f, e0 + 1.f))
                                    * __fdividef(1.f, 1.f + e1);
                }
                BARS(10, 512);
                BARA(1 + l, 1024);
                if (l < 7) {
                    const float4* w4 = (const float4*)(wres + (l * 64 + o) * 64 + p * 8);
                    const float4* g4 = (const float4*)(gvb + l * 64 + p * 8);
                    float ar = dot4(w4[0], g4[0]) + dot4(w4[1], g4[1]);
                    ar += __shfl_xor_sync(~0u, ar, 1);
                    ar += __shfl_xor_sync(~0u, ar, 2);
                    ar += __shfl_xor_sync(~0u, ar, 4);
                    if (p == 0) tcb[(l + 1) * 64 + o] = tcb[l * 64 + o] + ar;
                    BARS(11, 512);
                }
            }
            BARS(9, 1024);          // wait for B's hb
            {   // h2 = relu(wout @ hb)
                int o2 = tid >> 1, q = tid & 1;
                const float4* w4 = (const float4*)(wout + o2 * 256 + q * 128);
                const float4* v4 = (const float4*)(hb + q * 128);
                float acc = 0.f;
#pragma unroll
                for (int j = 0; j < 32; j++) acc += dot4(w4[j], v4[j]);
                acc += __shfl_xor_sync(~0u, acc, 1);
                if (q == 0) h2[o2] = fmaxf(acc, 0.f);
            }
            BARS(10, 512);
            {   // y = wend @ h2
                const float4* w4 = (const float4*)(wend + o * 256 + p * 32);
                const float4* v4 = (const float4*)(h2 + p * 32);
                float acc = 0.f;
#pragma unroll
                for (int j = 0; j < 8; j++) acc += dot4(w4[j], v4[j]);
                acc += __shfl_xor_sync(~0u, acc, 1);
                acc += __shfl_xor_sync(~0u, acc, 2);
                acc += __shfl_xor_sync(~0u, acc, 4);
                if (p == 0) {
                    yv[o] = acc;
                    g_outpre[(b * 64 + o) * 256 + n + 1] = acc;
                }
            }
            __syncthreads();
        }
    } else {
        // ------------- group B: ring writes, skip matvecs, cond prefetch
        const int t = tid - 512;
        const int s = t >> 1, q = t & 1;
        for (int n = 0; n < NSTEP; n++) {
#pragma unroll
            for (int l = 0; l < 8; l++) {
                BARS(1 + l, 1024);            // gv_l + tc_l ready, A's ring reads done
                const int slot = c_roff[l] + (n & (c_dil[l] - 1));
                if (t < 64) ring[slot * 64 + t] = tcb[l * 64 + t];
                const float4* w4 = (const float4*)(wskip + (l * 256 + s) * 64 + q * 32);
                const float4* g4 = (const float4*)(gvb + l * 64 + q * 32);
                float acc = 0.f;
#pragma unroll
                for (int j = 0; j < 8; j++) acc += dot4(w4[j], g4[j]);
                acc += __shfl_xor_sync(~0u, acc, 1);
                if (q == 0) skipv[s] += acc;
            }
            BARS(12, 512);                    // drain layer-7 skipv writes
            if (t < 256) { hb[t] = fmaxf(skipv[t], 0.f); skipv[t] = 0.f; }
            BARS(13, 512);                    // drain hb within B
            BARA(9, 1024);                    // release A's head
            if (n + 1 < NSTEP) {              // prefetch next cond column
                const float* gc = g_cond + ((n + 1) * 2 + b) * 1024;
                float* sn = sc + ((n + 1) & 1) * 1024;
                sn[t] = gc[t]; sn[512 + t] = gc[512 + t];
            }
            __syncthreads();
        }
    }
}

extern "C" void kernel_launch(void* const* d_in, const int* in_sizes, int n_in,
                              void* d_out, int out_size) {
    const float* song   = (const float*)d_in[0];
    const float* ds_w   = (const float*)d_in[1];
    const float* ds_g   = (const float*)d_in[2];
    const float* ds_b   = (const float*)d_in[3];
    const float* us_w   = (const float*)d_in[4];
    const float* us_g   = (const float*)d_in[5];
    const float* us_b   = (const float*)d_in[6];
    const float* wembed = (const float*)d_in[7];
    const float* wcond  = (const float*)d_in[8];
    const float* wdil   = (const float*)d_in[9];
    const float* wres   = (const float*)d_in[10];
    const float* wskip  = (const float*)d_in[11];
    const float* wout   = (const float*)d_in[12];
    const float* wend   = (const float*)d_in[13];
    float* out = (float*)d_out;

    cudaFuncSetAttribute(k_loop, cudaFuncAttributeMaxDynamicSharedMemorySize,
                         S_TOT * 4);

    k_downbn<<<64, 256>>>(0, ds_w, song, ds_g, ds_b);                  // 0
    k_downbn<<<64, 256>>>(1, ds_w + 8192, song, ds_g + 64, ds_b + 64); // 1
    k_wprep<<<512, 256>>>(wdil);                                       // 2
    k_cond<<<dim3(8, 16), 256>>>(wcond);                               // 3
    k_zero<<<1, 128>>>();                                              // 4
    k_loop<<<2, 1024, S_TOT * 4>>>(wembed, wres, wskip, wout, wend);   // 5
    k_upbn<<<64, 256>>>(0, us_w, us_g, us_b, nullptr);                 // 6
    k_upbn<<<64, 256>>>(1, us_w + 8192, us_g + 64, us_b + 64, out);    // 7
}

// round 7
// speedup vs baseline: 1.1839x; 1.0097x over previous
#include <cuda_runtime.h>

#define NSTEP 255

__device__ float g_wz[8 * 128 * 128];
__device__ float g_cond[NSTEP * 2 * 1024];
__device__ float g_ds1[2 * 64 * 512];
__device__ float g_ds2[2 * 64 * 256];
__device__ float g_outpre[2 * 64 * 256];
__device__ float g_up1[2 * 64 * 512];

__device__ __forceinline__ float dot4(float4 a, float4 x) {
    return a.x * x.x + a.y * x.y + a.z * x.z + a.w * x.w;
}
#define BARS(id, n) asm volatile("bar.sync %0,%1;" ::"r"(id), "r"(n) : "memory")
#define BARA(id, n) asm volatile("bar.arrive %0,%1;" ::"r"(id), "r"(n) : "memory")

// ---- fused down-conv + batchnorm + relu -----------------------------------
__global__ void k_downbn(int sel, const float* __restrict__ w,
                         const float* __restrict__ song,
                         const float* __restrict__ gamma,
                         const float* __restrict__ beta) {
    int o = blockIdx.x, tid = threadIdx.x;
    int Lout = sel ? 256 : 512;
    const float* in = sel ? g_ds1 : song;
    float* out = sel ? g_ds2 : g_ds1;
    __shared__ float wr[128], rs[256], rq[256];
    if (tid < 128) wr[tid] = w[o * 128 + tid];
    __syncthreads();
    float vals[4];
    int cnt = 2 * Lout / 256;
    float s = 0.f, q = 0.f;
    for (int j = 0; j < cnt; j++) {
        int i = tid + j * 256, bb = i >= Lout, l = i - bb * Lout;
        const float* xin = in + bb * 64 * 2 * Lout;
        float acc = 0.f;
#pragma unroll
        for (int c = 0; c < 64; c++)
            acc += wr[2 * c] * xin[c * 2 * Lout + 2 * l]
                 + wr[2 * c + 1] * xin[c * 2 * Lout + 2 * l + 1];
        vals[j] = acc; s += acc; q += acc * acc;
    }
    rs[tid] = s; rq[tid] = q; __syncthreads();
    for (int st = 128; st; st >>= 1) {
        if (tid < st) { rs[tid] += rs[tid + st]; rq[tid] += rq[tid + st]; }
        __syncthreads();
    }
    float m = rs[0] / (2.f * Lout);
    float inv = rsqrtf(rq[0] / (2.f * Lout) - m * m + 1e-5f);
    float ga = gamma[o], be = beta[o];
    for (int j = 0; j < cnt; j++) {
        int i = tid + j * 256, bb = i >= Lout, l = i - bb * Lout;
        out[(bb * 64 + o) * Lout + l] = fmaxf(ga * (vals[j] - m) * inv + be, 0.f);
    }
}

// ---- fused up-conv + batchnorm + relu -------------------------------------
__global__ void k_upbn(int sel, const float* __restrict__ w,
                       const float* __restrict__ gamma,
                       const float* __restrict__ beta, float* __restrict__ hout) {
    int o = blockIdx.x, tid = threadIdx.x;
    int Lin = sel ? 512 : 256;
    const float* in = sel ? g_up1 : g_outpre;
    float* out = sel ? hout : g_up1;
    __shared__ float wr[128], rs[256], rq[256];
    if (tid < 128) { int i = tid >> 1, k = tid & 1; wr[tid] = w[(i * 64 + o) * 2 + k]; }
    __syncthreads();
    int cnt = 2 * Lin / 256;
    float v0[4], v1[4];
    float s = 0.f, q = 0.f;
    for (int j = 0; j < cnt; j++) {
        int i = tid + j * 256, bb = i >= Lin, l = i - bb * Lin;
        float a0 = 0.f, a1 = 0.f;
#pragma unroll
        for (int c = 0; c < 64; c++) {
            float x = in[(bb * 64 + c) * Lin + l];
            a0 += wr[2 * c] * x; a1 += wr[2 * c + 1] * x;
        }
        v0[j] = a0; v1[j] = a1;
        s += a0 + a1; q += a0 * a0 + a1 * a1;
    }
    rs[tid] = s; rq[tid] = q; __syncthreads();
    for (int st = 128; st; st >>= 1) {
        if (tid < st) { rs[tid] += rs[tid + st]; rq[tid] += rq[tid + st]; }
        __syncthreads();
    }
    float m = rs[0] / (4.f * Lin);
    float inv = rsqrtf(rq[0] / (4.f * Lin) - m * m + 1e-5f);
    float ga = gamma[o], be = beta[o];
    for (int j = 0; j < cnt; j++) {
        int i = tid + j * 256, bb = i >= Lin, l = i - bb * Lin;
        float* op = out + (bb * 64 + o) * 2 * Lin + 2 * l;
        op[0] = fmaxf(ga * (v0[j] - m) * inv + be, 0.f);
        op[1] = fmaxf(ga * (v1[j] - m) * inv + be, 0.f);
    }
}

// ---- fused prep: w_dil transpose + cond GEMM + zero -----------------------
__global__ void k_prep(const float* __restrict__ wdil,
                       const float* __restrict__ wcond) {
    int bx = blockIdx.x, tid = threadIdx.x;
    if (bx >= 640) {                       // zero column 0 of outpre
        if (tid < 128) g_outpre[tid * 256] = 0.f;
        return;
    }
    if (bx >= 128) {                       // w_dil transpose
        int idx = (bx - 128) * 256 + tid;
        int r = idx & 63, t = (idx >> 6) & 1, o = (idx >> 7) & 127, l = idx >> 14;
        g_wz[idx] = wdil[((l * 128 + o) * 64 + r) * 2 + t];
        return;
    }
    // cond GEMM: blocks 0..127  (ob = (bx&7)*128, group = bx>>3)
    __shared__ __align__(16) float wt[128 * 64];
    __shared__ __align__(16) float col[128];
    int ob = (bx & 7) * 128, gy = bx >> 3;
    for (int i = tid; i < 128 * 64; i += 256) wt[i] = wcond[ob * 64 + i];
    for (int nn = 0; nn < 16; nn++) {
        int n = gy * 16 + nn;
        if (n >= NSTEP) break;
        __syncthreads();
        if (tid < 128) {
            int b = tid >> 6, c = tid & 63;
            col[tid] = g_ds2[(b * 64 + c) * 256 + n];
        }
        __syncthreads();
        int oo = tid >> 1, b = tid & 1;
        const float4* w4 = (const float4*)(wt + oo * 64);
        const float4* c4 = (const float4*)(col + b * 64);
        float acc = 0.f;
#pragma unroll
        for (int j = 0; j < 16; j++) acc += dot4(w4[j], c4[j]);
        g_cond[(n * 2 + b) * 1024 + ob + oo] = acc;
    }
}

// ---- autoregressive loop --------------------------------------------------
#define S_RING 0
#define S_SC   16320
#define S_GVB  18368
#define S_TCB  18880
#define S_SKIP 19456
#define S_HB   19712
#define S_H2   19968
#define S_YV   20224
#define S_TOT  20288

__constant__ int c_dil[8]  = {1, 2, 4, 8, 16, 32, 64, 128};
__constant__ int c_roff[8] = {0, 1, 3, 7, 15, 31, 63, 127};

__global__ void __launch_bounds__(1024, 1)
k_loop(const float* __restrict__ wembed, const float* __restrict__ wres,
       const float* __restrict__ wskip, const float* __restrict__ wout,
       const float* __restrict__ wend) {
    extern __shared__ float sm[];
    float* ring  = sm + S_RING;
    float* sc    = sm + S_SC;
    float* gvb   = sm + S_GVB;
    float* tcb   = sm + S_TCB;
    float* skipv = sm + S_SKIP;
    float* hb    = sm + S_HB;
    float* h2    = sm + S_H2;
    float* yv    = sm + S_YV;
    const int b = blockIdx.x, tid = threadIdx.x;

    for (int i = tid; i < 16320; i += 1024) ring[i] = 0.f;
    sc[tid] = g_cond[b * 1024 + tid];
    if (tid < 64) yv[tid] = 0.f;
    if (tid < 256) skipv[tid] = 0.f;
    __syncthreads();

    if (tid < 512) {
        // ---------------- group A: critical path -----------------------
        const int o = tid >> 3, p = tid & 7;
        const float4* gz4 = (const float4*)g_wz;
        const float4* wr4 = (const float4*)wres;
        const float4* we4 = (const float4*)wembed;
        const float4* wn4 = (const float4*)wend;
        const int zb0 = o * 32 + p * 4;            // z row o
        const int zb1 = (64 + o) * 32 + p * 4;     // z row o+64
        const int rb  = o * 16 + p * 2;            // res row o (per-layer +1024)
        float4 WA0 = gz4[zb0], WA1 = gz4[zb0 + 1], WA2 = gz4[zb0 + 2], WA3 = gz4[zb0 + 3];
        float4 WB0 = gz4[zb1], WB1 = gz4[zb1 + 1], WB2 = gz4[zb1 + 2], WB3 = gz4[zb1 + 3];
        float4 WR0 = wr4[rb], WR1 = wr4[rb + 1];

        for (int n = 0; n < NSTEP; n++) {
            const float* scur = sc + (n & 1) * 1024;
            {   // embed
                float4 e0 = we4[rb], e1 = we4[rb + 1];
                const float4* y4 = (const float4*)yv + p * 2;
                float acc = dot4(e0, y4[0]) + dot4(e1, y4[1]);
                acc += __shfl_xor_sync(~0u, acc, 1);
                acc += __shfl_xor_sync(~0u, acc, 2);
                acc += __shfl_xor_sync(~0u, acc, 4);
                if (p == 0) tcb[o] = acc;
            }
            BARS(11, 512);
#pragma unroll
            for (int l = 0; l < 8; l++) {
                const int slot = c_roff[l] + (n & (c_dil[l] - 1));
                const float4* v4 = (p < 4)
                    ? (const float4*)(ring + slot * 64 + p * 16)
                    : (const float4*)(tcb + l * 64 + (p - 4) * 16);
                float4 x0 = v4[0], x1 = v4[1], x2 = v4[2], x3 = v4[3];
                float a0 = dot4(WA0, x0) + dot4(WA1, x1);
                float a0b = dot4(WA2, x2) + dot4(WA3, x3);
                float a1 = dot4(WB0, x0) + dot4(WB1, x1);
                float a1b = dot4(WB2, x2) + dot4(WB3, x3);
                // JIT reload: next layer's z weights, or wend at l==7
                if (l < 7) {
                    int nb0 = (l + 1) * 4096 + zb0, nb1 = (l + 1) * 4096 + zb1;
                    WA0 = gz4[nb0]; WA1 = gz4[nb0 + 1]; WA2 = gz4[nb0 + 2]; WA3 = gz4[nb0 + 3];
                    WB0 = gz4[nb1]; WB1 = gz4[nb1 + 1]; WB2 = gz4[nb1 + 2]; WB3 = gz4[nb1 + 3];
                } else {
                    int hbi = o * 64 + p * 8;
                    WA0 = wn4[hbi];     WA1 = wn4[hbi + 1]; WA2 = wn4[hbi + 2]; WA3 = wn4[hbi + 3];
                    WB0 = wn4[hbi + 4]; WB1 = wn4[hbi + 5]; WB2 = wn4[hbi + 6]; WB3 = wn4[hbi + 7];
                }
                a0 += a0b; a1 += a1b;
                a0 += __shfl_xor_sync(~0u, a0, 1); a1 += __shfl_xor_sync(~0u, a1, 1);
                a0 += __shfl_xor_sync(~0u, a0, 2); a1 += __shfl_xor_sync(~0u, a1, 2);
                a0 += __shfl_xor_sync(~0u, a0, 4); a1 += __shfl_xor_sync(~0u, a1, 4);
                if (p == 0) {
                    float z0 = a0 + scur[l * 128 + o];
                    float z1 = a1 + scur[l * 128 + 64 + o];
                    float e0 = __expf(2.f * z0), e1 = __expf(-z1);
                    gvb[l * 64 + o] = (1.f - __fdividef(2.f, e0 + 1.f))
                                    * __fdividef(1.f, 1.f + e1);
                }
                BARS(10, 512);
                BARA(1 + l, 1024);
                if (l < 7) {
                    const float4* g4 = (const float4*)(gvb + l * 64) + p * 2;
                    float ar = dot4(WR0, g4[0]) + dot4(WR1, g4[1]);
                    WR0 = wr4[(l + 1) * 1024 + rb]; WR1 = wr4[(l + 1) * 1024 + rb + 1];
                    ar += __shfl_xor_sync(~0u, ar, 1);
                    ar += __shfl_xor_sync(~0u, ar, 2);
                    ar += __shfl_xor_sync(~0u, ar, 4);
                    if (p == 0) tcb[(l + 1) * 64 + o] = tcb[l * 64 + o] + ar;
                    BARS(11, 512);
                } else {
                    WR0 = wr4[rb]; WR1 = wr4[rb + 1];    // layer 0, next step
                }
            }
            BARS(9, 1024);          // wait for B's hb
            {   // h2 = relu(wout @ hb), 4 accumulators
                int o2 = tid >> 1, q = tid & 1;
                const float4* w4 = (const float4*)wout + o2 * 64 + q * 32;
                const float4* v4 = (const float4*)hb + q * 32;
                float c0 = 0.f, c1 = 0.f, c2 = 0.f, c3 = 0.f;
#pragma unroll
                for (int j = 0; j < 8; j++) {
                    c0 += dot4(w4[4 * j], v4[4 * j]);
                    c1 += dot4(w4[4 * j + 1], v4[4 * j + 1]);
                    c2 += dot4(w4[4 * j + 2], v4[4 * j + 2]);
                    c3 += dot4(w4[4 * j + 3], v4[4 * j + 3]);
                }
                float acc = (c0 + c1) + (c2 + c3);
                acc += __shfl_xor_sync(~0u, acc, 1);
                if (q == 0) h2[o2] = fmaxf(acc, 0.f);
            }
            BARS(10, 512);
            {   // y = wend @ h2  (weights already in WA/WB from l==7 prefetch)
                const float4* h4 = (const float4*)h2 + p * 8;
                float y0 = dot4(WA0, h4[0]) + dot4(WA1, h4[1]);
                float y1 = dot4(WA2, h4[2]) + dot4(WA3, h4[3]);
                y0 += dot4(WB0, h4[4]) + dot4(WB1, h4[5]);
                y1 += dot4(WB2, h4[6]) + dot4(WB3, h4[7]);
                float acc = y0 + y1;
                acc += __shfl_xor_sync(~0u, acc, 1);
                acc += __shfl_xor_sync(~0u, acc, 2);
                acc += __shfl_xor_sync(~0u, acc, 4);
                if (p == 0) {
                    yv[o] = acc;
                    g_outpre[(b * 64 + o) * 256 + n + 1] = acc;
                }
            }
            // reload layer-0 z weights for next step (overlaps sync + embed)
            WA0 = gz4[zb0]; WA1 = gz4[zb0 + 1]; WA2 = gz4[zb0 + 2]; WA3 = gz4[zb0 + 3];
            WB0 = gz4[zb1]; WB1 = gz4[zb1 + 1]; WB2 = gz4[zb1 + 2]; WB3 = gz4[zb1 + 3];
            __syncthreads();
        }
    } else {
        // ---------------- group B: rings, skip, cond prefetch ----------
        const int t = tid - 512;
        const int s = t >> 1, q = t & 1;
        const float4* ws4 = (const float4*)wskip;
        const int sb = s * 16 + q * 8;              // per-layer + l*4096
        float4 S0 = ws4[sb],     S1 = ws4[sb + 1], S2 = ws4[sb + 2], S3 = ws4[sb + 3];
        float4 S4 = ws4[sb + 4], S5 = ws4[sb + 5], S6 = ws4[sb + 6], S7 = ws4[sb + 7];
        for (int n = 0; n < NSTEP; n++) {
#pragma unroll
            for (int l = 0; l < 8; l++) {
                BARS(1 + l, 1024);
                const int slot = c_roff[l] + (n & (c_dil[l] - 1));
                if (t < 64) ring[slot * 64 + t] = tcb[l * 64 + t];
                const float4* g4 = (const float4*)(gvb + l * 64) + q * 8;
                float c0 = dot4(S0, g4[0]) + dot4(S1, g4[1])
                         + dot4(S2, g4[2]) + dot4(S3, g4[3]);
                float c1 = dot4(S4, g4[4]) + dot4(S5, g4[5])
                         + dot4(S6, g4[6]) + dot4(S7, g4[7]);
                int ln = (l < 7) ? l + 1 : 0;
                int nb = ln * 4096 + sb;
                S0 = ws4[nb];     S1 = ws4[nb + 1]; S2 = ws4[nb + 2]; S3 = ws4[nb + 3];
                S4 = ws4[nb + 4]; S5 = ws4[nb + 5]; S6 = ws4[nb + 6]; S7 = ws4[nb + 7];
                float acc = c0 + c1;
                acc += __shfl_xor_sync(~0u, acc, 1);
                if (q == 0) skipv[s] += acc;
            }
            BARS(12, 512);
            if (t < 256) { hb[t] = fmaxf(skipv[t], 0.f); skipv[t] = 0.f; }
            BARS(13, 512);
            BARA(9, 1024);
            if (n + 1 < NSTEP) {
                const float* gc = g_cond + ((n + 1) * 2 + b) * 1024;
                float* sn = sc + ((n + 1) & 1) * 1024;
                sn[t] = gc[t]; sn[512 + t] = gc[512 + t];
            }
            __syncthreads();
        }
    }
}

extern "C" void kernel_launch(void* const* d_in, const int* in_sizes, int n_in,
                              void* d_out, int out_size) {
    const float* song   = (const float*)d_in[0];
    const float* ds_w   = (const float*)d_in[1];
    const float* ds_g   = (const float*)d_in[2];
    const float* ds_b   = (const float*)d_in[3];
    const float* us_w   = (const float*)d_in[4];
    const float* us_g   = (const float*)d_in[5];
    const float* us_b   = (const float*)d_in[6];
    const float* wembed = (const float*)d_in[7];
    const float* wcond  = (const float*)d_in[8];
    const float* wdil   = (const float*)d_in[9];
    const float* wres   = (const float*)d_in[10];
    const float* wskip  = (const float*)d_in[11];
    const float* wout   = (const float*)d_in[12];
    const float* wend   = (const float*)d_in[13];
    float* out = (float*)d_out;

    cudaFuncSetAttribute(k_loop, cudaFuncAttributeMaxDynamicSharedMemorySize,
                         S_TOT * 4);

    k_downbn<<<64, 256>>>(0, ds_w, song, ds_g, ds_b);                  // 0
    k_downbn<<<64, 256>>>(1, ds_w + 8192, song, ds_g + 64, ds_b + 64); // 1
    k_prep<<<641, 256>>>(wdil, wcond);                                 // 2
    k_loop<<<2, 1024, S_TOT * 4>>>(wembed, wres, wskip, wout, wend);   // 3 <- profiled
    k_upbn<<<64, 256>>>(0, us_w, us_g, us_b, nullptr);                 // 4
    k_upbn<<<64, 256>>>(1, us_w + 8192, us_g + 64, us_b + 64, out);    // 5
}